// round 13
// baseline (speedup 1.0000x reference)
#include <cuda_runtime.h>

// UndistortLayer: B=16, C=3, H=W=512, fp32.
// 1 thread = 8 vertically adjacent pixels (same x), processed in 4 row-PAIRS:
// both rows' indices+weights computed, all 24 gathers issued together, then
// both rows reduced. __launch_bounds__(256,6): ~42-reg budget -> partial pair
// overlap without the occupancy crash of minblocks=4 (regs=64, occ 41%, R12)
// and without the full serialization of regs=32 (R11).
// Lanes consecutive in x (warp x-span 32 -> ~2 L1 wavefronts per gather LDG).
// Map: px=x-dx-256, d=1-(k/512^2)(px^2+py^2), xd=px/d+cx, yd=py/d+cy.
// One-sided clamps (k<0 contraction keeps xd,yd in [0,511]).
// Gathers: L1::evict_last. Stores: .cs streaming.

#define UD_W 512
#define UD_HW (512 * 512)            // 2^18
#define UD_CHW (3 * UD_HW)
#define ROWS 8

__device__ __forceinline__ float ldg_el(const float* p) {
    float v;
    asm("ld.global.nc.L1::evict_last.f32 %0, [%1];" : "=f"(v) : "l"(p));
    return v;
}
__device__ __forceinline__ void stg_cs(float* p, float v) {
    asm volatile("st.global.cs.f32 [%0], %1;" :: "l"(p), "f"(v));
}

__global__ __launch_bounds__(256, 6) void undistort_kernel(
    const float* __restrict__ im,   // [B, 3, H, W]
    const float* __restrict__ kArr, // [B]
    const float* __restrict__ dxArr,// [B]
    const float* __restrict__ dyArr,// [B]
    float* __restrict__ out)        // [B, 3, H, W]
{
    const int t  = blockIdx.x * 256 + threadIdx.x;
    const int x  = t & 511;               // lane-consecutive x
    const int yo = (t >> 9) & 63;         // y-octet index
    const int b  = t >> 15;
    const int y0 = yo << 3;

    const float k  = __ldg(&kArr[b]);
    const float dx = __ldg(&dxArr[b]);
    const float dy = __ldg(&dyArr[b]);

    const float kw = k * (1.0f / (512.0f * 512.0f));
    const float cx = 256.0f + dx;
    const float cy = 256.0f + dy;
    const float px = (float)x - cx;
    const float px2 = px * px;

    const float* imb = im + (size_t)b * UD_CHW;
    float* outb = out + (size_t)b * UD_CHW + (size_t)y0 * UD_W + x;

    float py = (float)y0 - cy;

    #pragma unroll
    for (int ip = 0; ip < ROWS / 2; ++ip) {
        // ---- indices + weights for the row pair ----
        int i00p[2], xsp[2], ysp[2];
        float w00p[2], w01p[2], w10p[2], w11p[2];

        #pragma unroll
        for (int r = 0; r < 2; ++r) {
            const float d  = fmaf(-kw, fmaf(py, py, px2), 1.0f);
            const float inv = __fdividef(1.0f, d);
            const float xd = fmaf(px, inv, cx);
            const float yd = fmaf(py, inv, cy);
            py += 1.0f;

            const int xfu = __float2int_rd(xd);
            const int yfu = __float2int_rd(yd);
            const float ox = xd - (float)xfu;
            const float oy = yd - (float)yfu;

            const int xfi = max(xfu, 0);
            const int yfi = max(yfu, 0);
            xsp[r] = min(xfu + 1, 511) - xfi;               // 0 or 1
            ysp[r] = (min(yfu + 1, 511) - yfi) << 9;        // 0 or 512
            i00p[r] = (yfi << 9) + xfi;

            w00p[r] = (1.0f - ox) * (1.0f - oy);
            w01p[r] = ox * (1.0f - oy);
            w10p[r] = (1.0f - ox) * oy;
            w11p[r] = ox * oy;
        }

        // ---- issue all 24 gathers for both rows ----
        float v[2][3][4];
        #pragma unroll
        for (int r = 0; r < 2; ++r) {
            const int i00 = i00p[r];
            const int i01 = i00 + xsp[r];
            const int i10 = i00 + ysp[r];
            const int i11 = i10 + xsp[r];
            #pragma unroll
            for (int c = 0; c < 3; ++c) {
                const float* pl = imb + c * UD_HW;
                v[r][c][0] = ldg_el(pl + i00);
                v[r][c][1] = ldg_el(pl + i01);
                v[r][c][2] = ldg_el(pl + i10);
                v[r][c][3] = ldg_el(pl + i11);
            }
        }

        // ---- reduce + store both rows ----
        #pragma unroll
        for (int r = 0; r < 2; ++r) {
            float* orow = outb + (2 * ip + r) * UD_W;
            #pragma unroll
            for (int c = 0; c < 3; ++c) {
                stg_cs(orow + c * UD_HW,
                       fmaf(w00p[r], v[r][c][0],
                       fmaf(w01p[r], v[r][c][1],
                       fmaf(w10p[r], v[r][c][2],
                            w11p[r] * v[r][c][3]))));
            }
        }
    }
}

extern "C" void kernel_launch(void* const* d_in, const int* in_sizes, int n_in,
                              void* d_out, int out_size) {
    const float* im = (const float*)d_in[0];
    const float* k  = (const float*)d_in[1];
    const float* dx = (const float*)d_in[2];
    const float* dy = (const float*)d_in[3];
    float* out = (float*)d_out;

    const int total_threads = 16 * UD_HW / ROWS;   // 524,288
    const int block = 256;
    const int grid = total_threads / block;        // 2048
    undistort_kernel<<<grid, block>>>(im, k, dx, dy, out);
}

// round 14
// speedup vs baseline: 1.0543x; 1.0543x over previous
#include <cuda_runtime.h>

// UndistortLayer: B=16, C=3, H=W=512, fp32.
// 1 thread = 4 vertically adjacent pixels (same x), processed in 2 row-PAIRS
// (both rows' indices+weights computed, 24 gathers issued together, then both
// reduced). ROWS=4 keeps the per-SM resident source footprint ~100KB << 228KB
// L1 (ROWS=8 was ~200KB ~= L1 size -> thrash), so evict_last gathers actually
// stay resident. regs=32 / no minblocks cap -> 64 warps/SM (HW max).
// Lanes consecutive in x (warp x-span 32 -> ~2 L1 wavefronts per gather LDG).
// Map: px=x-dx-256, d=1-(k/512^2)(px^2+py^2), xd=px/d+cx, yd=py/d+cy.
// One-sided clamps (k<0 contraction keeps xd,yd in [0,511]).
// Gathers: L1::evict_last. Stores: .cs streaming (output never re-read).

#define UD_W 512
#define UD_HW (512 * 512)            // 2^18
#define UD_CHW (3 * UD_HW)
#define ROWS 4

__device__ __forceinline__ float ldg_el(const float* p) {
    float v;
    asm("ld.global.nc.L1::evict_last.f32 %0, [%1];" : "=f"(v) : "l"(p));
    return v;
}
__device__ __forceinline__ void stg_cs(float* p, float v) {
    asm volatile("st.global.cs.f32 [%0], %1;" :: "l"(p), "f"(v));
}

__global__ __launch_bounds__(256) void undistort_kernel(
    const float* __restrict__ im,   // [B, 3, H, W]
    const float* __restrict__ kArr, // [B]
    const float* __restrict__ dxArr,// [B]
    const float* __restrict__ dyArr,// [B]
    float* __restrict__ out)        // [B, 3, H, W]
{
    const int t  = blockIdx.x * 256 + threadIdx.x;
    const int x  = t & 511;               // lane-consecutive x
    const int yq = (t >> 9) & 127;        // y-quad index
    const int b  = t >> 16;
    const int y0 = yq << 2;

    const float k  = __ldg(&kArr[b]);
    const float dx = __ldg(&dxArr[b]);
    const float dy = __ldg(&dyArr[b]);

    const float kw = k * (1.0f / (512.0f * 512.0f));
    const float cx = 256.0f + dx;
    const float cy = 256.0f + dy;
    const float px = (float)x - cx;
    const float px2 = px * px;

    const float* imb = im + (size_t)b * UD_CHW;
    float* outb = out + (size_t)b * UD_CHW + (size_t)y0 * UD_W + x;

    float py = (float)y0 - cy;

    #pragma unroll
    for (int ip = 0; ip < ROWS / 2; ++ip) {
        // ---- indices + weights for the row pair ----
        int i00p[2], xsp[2], ysp[2];
        float w00p[2], w01p[2], w10p[2], w11p[2];

        #pragma unroll
        for (int r = 0; r < 2; ++r) {
            const float d  = fmaf(-kw, fmaf(py, py, px2), 1.0f);
            const float inv = __fdividef(1.0f, d);
            const float xd = fmaf(px, inv, cx);
            const float yd = fmaf(py, inv, cy);
            py += 1.0f;

            const int xfu = __float2int_rd(xd);
            const int yfu = __float2int_rd(yd);
            const float ox = xd - (float)xfu;
            const float oy = yd - (float)yfu;

            const int xfi = max(xfu, 0);
            const int yfi = max(yfu, 0);
            xsp[r] = min(xfu + 1, 511) - xfi;               // 0 or 1
            ysp[r] = (min(yfu + 1, 511) - yfi) << 9;        // 0 or 512
            i00p[r] = (yfi << 9) + xfi;

            w00p[r] = (1.0f - ox) * (1.0f - oy);
            w01p[r] = ox * (1.0f - oy);
            w10p[r] = (1.0f - ox) * oy;
            w11p[r] = ox * oy;
        }

        // ---- issue all 24 gathers for both rows ----
        float v[2][3][4];
        #pragma unroll
        for (int r = 0; r < 2; ++r) {
            const int i00 = i00p[r];
            const int i01 = i00 + xsp[r];
            const int i10 = i00 + ysp[r];
            const int i11 = i10 + xsp[r];
            #pragma unroll
            for (int c = 0; c < 3; ++c) {
                const float* pl = imb + c * UD_HW;
                v[r][c][0] = ldg_el(pl + i00);
                v[r][c][1] = ldg_el(pl + i01);
                v[r][c][2] = ldg_el(pl + i10);
                v[r][c][3] = ldg_el(pl + i11);
            }
        }

        // ---- reduce + store both rows ----
        #pragma unroll
        for (int r = 0; r < 2; ++r) {
            float* orow = outb + (2 * ip + r) * UD_W;
            #pragma unroll
            for (int c = 0; c < 3; ++c) {
                stg_cs(orow + c * UD_HW,
                       fmaf(w00p[r], v[r][c][0],
                       fmaf(w01p[r], v[r][c][1],
                       fmaf(w10p[r], v[r][c][2],
                            w11p[r] * v[r][c][3]))));
            }
        }
    }
}

extern "C" void kernel_launch(void* const* d_in, const int* in_sizes, int n_in,
                              void* d_out, int out_size) {
    const float* im = (const float*)d_in[0];
    const float* k  = (const float*)d_in[1];
    const float* dx = (const float*)d_in[2];
    const float* dy = (const float*)d_in[3];
    float* out = (float*)d_out;

    const int total_threads = 16 * UD_HW / ROWS;   // 1,048,576
    const int block = 256;
    const int grid = total_threads / block;        // 4096
    undistort_kernel<<<grid, block>>>(im, k, dx, dy, out);
}

// round 15
// speedup vs baseline: 1.0595x; 1.0050x over previous
#include <cuda_runtime.h>

// UndistortLayer: B=16, C=3, H=W=512, fp32.
// 1 thread = 8 vertically adjacent pixels (same x), processed in 4 row-PAIRS:
// both rows' indices+weights computed, all 24 gathers issued together, then
// both rows reduced. Lanes consecutive in x (warp x-span 32 -> minimal ~2 L1
// wavefronts per gather LDG). block=128: same 64 warps/SM occupancy, but 2x
// finer block scheduling granularity (tail smoothing across ~3.5 waves).
// Map: px=x-dx-256, d=1-(k/512^2)(px^2+py^2), xd=px/d+cx, yd=py/d+cy.
// One-sided clamps (k<0 contraction keeps xd,yd in [0,511]).
// Gathers: L1::evict_last (cross-warp line reuse). Stores: .cs streaming.

#define UD_W 512
#define UD_HW (512 * 512)            // 2^18
#define UD_CHW (3 * UD_HW)
#define ROWS 8
#define BLK 128

__device__ __forceinline__ float ldg_el(const float* p) {
    float v;
    asm("ld.global.nc.L1::evict_last.f32 %0, [%1];" : "=f"(v) : "l"(p));
    return v;
}
__device__ __forceinline__ void stg_cs(float* p, float v) {
    asm volatile("st.global.cs.f32 [%0], %1;" :: "l"(p), "f"(v));
}

__global__ __launch_bounds__(BLK) void undistort_kernel(
    const float* __restrict__ im,   // [B, 3, H, W]
    const float* __restrict__ kArr, // [B]
    const float* __restrict__ dxArr,// [B]
    const float* __restrict__ dyArr,// [B]
    float* __restrict__ out)        // [B, 3, H, W]
{
    const int t  = blockIdx.x * BLK + threadIdx.x;
    const int x  = t & 511;               // lane-consecutive x
    const int yo = (t >> 9) & 63;         // y-octet index
    const int b  = t >> 15;
    const int y0 = yo << 3;

    const float k  = __ldg(&kArr[b]);
    const float dx = __ldg(&dxArr[b]);
    const float dy = __ldg(&dyArr[b]);

    const float kw = k * (1.0f / (512.0f * 512.0f));
    const float cx = 256.0f + dx;
    const float cy = 256.0f + dy;
    const float px = (float)x - cx;
    const float px2 = px * px;

    const float* imb = im + (size_t)b * UD_CHW;
    float* outb = out + (size_t)b * UD_CHW + (size_t)y0 * UD_W + x;

    float py = (float)y0 - cy;

    #pragma unroll
    for (int ip = 0; ip < ROWS / 2; ++ip) {
        // ---- indices + weights for the row pair ----
        int i00p[2], xsp[2], ysp[2];
        float w00p[2], w01p[2], w10p[2], w11p[2];

        #pragma unroll
        for (int r = 0; r < 2; ++r) {
            const float d  = fmaf(-kw, fmaf(py, py, px2), 1.0f);
            const float inv = __fdividef(1.0f, d);
            const float xd = fmaf(px, inv, cx);
            const float yd = fmaf(py, inv, cy);
            py += 1.0f;

            const int xfu = __float2int_rd(xd);
            const int yfu = __float2int_rd(yd);
            const float ox = xd - (float)xfu;
            const float oy = yd - (float)yfu;

            const int xfi = max(xfu, 0);
            const int yfi = max(yfu, 0);
            xsp[r] = min(xfu + 1, 511) - xfi;               // 0 or 1
            ysp[r] = (min(yfu + 1, 511) - yfi) << 9;        // 0 or 512
            i00p[r] = (yfi << 9) + xfi;

            w00p[r] = (1.0f - ox) * (1.0f - oy);
            w01p[r] = ox * (1.0f - oy);
            w10p[r] = (1.0f - ox) * oy;
            w11p[r] = ox * oy;
        }

        // ---- issue all 24 gathers for both rows ----
        float v[2][3][4];
        #pragma unroll
        for (int r = 0; r < 2; ++r) {
            const int i00 = i00p[r];
            const int i01 = i00 + xsp[r];
            const int i10 = i00 + ysp[r];
            const int i11 = i10 + xsp[r];
            #pragma unroll
            for (int c = 0; c < 3; ++c) {
                const float* pl = imb + c * UD_HW;
                v[r][c][0] = ldg_el(pl + i00);
                v[r][c][1] = ldg_el(pl + i01);
                v[r][c][2] = ldg_el(pl + i10);
                v[r][c][3] = ldg_el(pl + i11);
            }
        }

        // ---- reduce + store both rows ----
        #pragma unroll
        for (int r = 0; r < 2; ++r) {
            float* orow = outb + (2 * ip + r) * UD_W;
            #pragma unroll
            for (int c = 0; c < 3; ++c) {
                stg_cs(orow + c * UD_HW,
                       fmaf(w00p[r], v[r][c][0],
                       fmaf(w01p[r], v[r][c][1],
                       fmaf(w10p[r], v[r][c][2],
                            w11p[r] * v[r][c][3]))));
            }
        }
    }
}

extern "C" void kernel_launch(void* const* d_in, const int* in_sizes, int n_in,
                              void* d_out, int out_size) {
    const float* im = (const float*)d_in[0];
    const float* k  = (const float*)d_in[1];
    const float* dx = (const float*)d_in[2];
    const float* dy = (const float*)d_in[3];
    float* out = (float*)d_out;

    const int total_threads = 16 * UD_HW / ROWS;   // 524,288
    const int grid = total_threads / BLK;          // 4096
    undistort_kernel<<<grid, BLK>>>(im, k, dx, dy, out);
}